// round 7
// baseline (speedup 1.0000x reference)
#include <cuda_runtime.h>
#include <math.h>

// Problem constants
constexpr int B = 4, S = 2048, E = 1024, H = 16, D = 64;
constexpr int M_ROWS = B * S;   // 8192

// ---------------------------------------------------------------------------
// Device-global scratch (allocation-free rule)
// ---------------------------------------------------------------------------
__device__ float g_xhi[(size_t)M_ROWS * E], g_xlo[(size_t)M_ROWS * E];
__device__ float g_Whi[4][(size_t)E * E],   g_Wlo[4][(size_t)E * E];
__device__ float g_qhi[(size_t)M_ROWS * E], g_qlo[(size_t)M_ROWS * E];  // (B,H,S,D)
__device__ float g_khi[(size_t)M_ROWS * E], g_klo[(size_t)M_ROWS * E];
__device__ float g_vhi[(size_t)M_ROWS * E], g_vlo[(size_t)M_ROWS * E];
__device__ float g_chi[(size_t)M_ROWS * E], g_clo[(size_t)M_ROWS * E];  // (B,S,E)

// ---------------------------------------------------------------------------
// tf32 helpers (3xTF32: hi*hi + hi*lo + lo*hi, fp32-level accuracy)
// ---------------------------------------------------------------------------
__device__ __forceinline__ void split_tf32(float x, unsigned& hi, unsigned& lo) {
    unsigned h;
    asm("cvt.rna.tf32.f32 %0, %1;" : "=r"(h) : "f"(x));
    float r = x - __uint_as_float(h);
    unsigned l;
    asm("cvt.rna.tf32.f32 %0, %1;" : "=r"(l) : "f"(r));
    hi = h; lo = l;
}

__device__ __forceinline__ void mma_tf32(float c[4],
                                         const unsigned a[4],
                                         unsigned b0, unsigned b1) {
    asm volatile(
        "mma.sync.aligned.m16n8k8.row.col.f32.tf32.tf32.f32 "
        "{%0,%1,%2,%3}, {%4,%5,%6,%7}, {%8,%9}, {%0,%1,%2,%3};"
        : "+f"(c[0]), "+f"(c[1]), "+f"(c[2]), "+f"(c[3])
        : "r"(a[0]), "r"(a[1]), "r"(a[2]), "r"(a[3]), "r"(b0), "r"(b1));
}

__device__ __forceinline__ unsigned fbits(float x) { return __float_as_uint(x); }

#define CP_ASYNC16(dst_u32, src_ptr) \
    asm volatile("cp.async.cg.shared.global [%0], [%1], 16;\n" :: "r"(dst_u32), "l"(src_ptr) : "memory")
#define CP_COMMIT() asm volatile("cp.async.commit_group;\n" ::: "memory")
#define CP_WAIT0()  asm volatile("cp.async.wait_group 0;\n" ::: "memory")

// ---------------------------------------------------------------------------
// Split kernel: src -> (tf32 hi, tf32 lo), vectorized
// ---------------------------------------------------------------------------
__global__ __launch_bounds__(256) void split_kernel(
    const float* __restrict__ src, float* __restrict__ hi,
    float* __restrict__ lo, int n4)
{
    const int i = blockIdx.x * 256 + threadIdx.x;
    if (i >= n4) return;
    float4 v = ((const float4*)src)[i];
    float4 h, l;
    unsigned hu, lu;
    split_tf32(v.x, hu, lu); h.x = __uint_as_float(hu); l.x = __uint_as_float(lu);
    split_tf32(v.y, hu, lu); h.y = __uint_as_float(hu); l.y = __uint_as_float(lu);
    split_tf32(v.z, hu, lu); h.z = __uint_as_float(hu); l.z = __uint_as_float(lu);
    split_tf32(v.w, hu, lu); h.w = __uint_as_float(hu); l.w = __uint_as_float(lu);
    ((float4*)hi)[i] = h;
    ((float4*)lo)[i] = l;
}

// ---------------------------------------------------------------------------
// GEMM: C = scale*(A(MxE) @ W(ExE) + bias), A and W given pre-split (hi/lo).
// CTA 128x128, BK=32, 256 threads = 8 warps (2x4), warp tile 64x32.
// Inner loop: LDS + HMMA only (no cvt).
// MODE 0: write single fp32 C row-major (M x E)
// MODE 1: write split Chi/Clo in head layout (B,H,S,D)
// ---------------------------------------------------------------------------
constexpr int GBM = 128, GBN = 128, GBK = 32;
constexpr int ASTR = 36, BSTR = 132;
constexpr int A_BUF = GBM * ASTR;   // 4608 floats
constexpr int B_BUF = GBK * BSTR;   // 4224 floats
// floats: AHI[2] | ALO[2] | BHI[2] | BLO[2]
constexpr int OF_AHI = 0;
constexpr int OF_ALO = 2 * A_BUF;
constexpr int OF_BHI = 4 * A_BUF;
constexpr int OF_BLO = 4 * A_BUF + 2 * B_BUF;
constexpr int GEMM_SMEM_BYTES = (4 * A_BUF + 4 * B_BUF) * 4;  // 141312

template <int MODE>
__global__ __launch_bounds__(256) void gemm3_kernel(
    const float* __restrict__ Ahi, const float* __restrict__ Alo,
    const float* __restrict__ Whi, const float* __restrict__ Wlo,
    const float* __restrict__ bias, float scale,
    float* __restrict__ Chi, float* __restrict__ Clo)
{
    extern __shared__ float smem[];
    const int tid = threadIdx.x;
    const int warpId = tid >> 5, lane = tid & 31;
    const int wm = warpId >> 2, wn = warpId & 3;
    const int gID = lane >> 2, tig = lane & 3;

    const int bx = blockIdx.x, by = blockIdx.y;
    const float* AhiG = Ahi + (size_t)(by * GBM) * E;
    const float* AloG = Alo + (size_t)(by * GBM) * E;
    const float* WhiG = Whi + bx * GBN;
    const float* WloG = Wlo + bx * GBN;

    float acc[4][4][4];
#pragma unroll
    for (int mt = 0; mt < 4; mt++)
#pragma unroll
        for (int nt = 0; nt < 4; nt++)
#pragma unroll
            for (int r = 0; r < 4; r++) acc[mt][nt][r] = 0.0f;

    const int a_r = tid >> 3, a_c = (tid & 7) * 4;   // A tile 128x32
    const int b_r = tid >> 5, b_c = (tid & 31) * 4;  // B tile 32x128

    auto load_tile = [&](int t, int buf) {
#pragma unroll
        for (int it = 0; it < 4; it++) {
            const int r = a_r + it * 32;
            const size_t g = (size_t)r * E + t * GBK + a_c;
            unsigned dh = (unsigned)__cvta_generic_to_shared(
                &smem[OF_AHI + buf * A_BUF + r * ASTR + a_c]);
            CP_ASYNC16(dh, AhiG + g);
            unsigned dl = (unsigned)__cvta_generic_to_shared(
                &smem[OF_ALO + buf * A_BUF + r * ASTR + a_c]);
            CP_ASYNC16(dl, AloG + g);
        }
#pragma unroll
        for (int it = 0; it < 4; it++) {
            const int r = b_r + it * 8;
            const size_t g = (size_t)(t * GBK + r) * E + b_c;
            unsigned dh = (unsigned)__cvta_generic_to_shared(
                &smem[OF_BHI + buf * B_BUF + r * BSTR + b_c]);
            CP_ASYNC16(dh, WhiG + g);
            unsigned dl = (unsigned)__cvta_generic_to_shared(
                &smem[OF_BLO + buf * B_BUF + r * BSTR + b_c]);
            CP_ASYNC16(dl, WloG + g);
        }
    };

    constexpr int T = E / GBK;   // 32
    load_tile(0, 0);
    CP_COMMIT();

    for (int t = 0; t < T; t++) {
        const int buf = t & 1;
        CP_WAIT0();
        __syncthreads();
        if (t + 1 < T) {
            load_tile(t + 1, buf ^ 1);
            CP_COMMIT();
        }

        const float* AbH = smem + OF_AHI + buf * A_BUF + (wm * 64) * ASTR;
        const float* AbL = smem + OF_ALO + buf * A_BUF + (wm * 64) * ASTR;
        const float* BbH = smem + OF_BHI + buf * B_BUF + wn * 32;
        const float* BbL = smem + OF_BLO + buf * B_BUF + wn * 32;

#pragma unroll
        for (int k8 = 0; k8 < 4; k8++) {
            const int kb = k8 * 8;
            unsigned ah[4][4], al[4][4];
#pragma unroll
            for (int mt = 0; mt < 4; mt++) {
                const int r0 = mt * 16 + gID;
                ah[mt][0] = fbits(AbH[(r0    ) * ASTR + kb + tig    ]);
                ah[mt][1] = fbits(AbH[(r0 + 8) * ASTR + kb + tig    ]);
                ah[mt][2] = fbits(AbH[(r0    ) * ASTR + kb + tig + 4]);
                ah[mt][3] = fbits(AbH[(r0 + 8) * ASTR + kb + tig + 4]);
                al[mt][0] = fbits(AbL[(r0    ) * ASTR + kb + tig    ]);
                al[mt][1] = fbits(AbL[(r0 + 8) * ASTR + kb + tig    ]);
                al[mt][2] = fbits(AbL[(r0    ) * ASTR + kb + tig + 4]);
                al[mt][3] = fbits(AbL[(r0 + 8) * ASTR + kb + tig + 4]);
            }
            unsigned bh[4][2], bl[4][2];
#pragma unroll
            for (int nt = 0; nt < 4; nt++) {
                const int n0 = nt * 8 + gID;
                bh[nt][0] = fbits(BbH[(kb + tig    ) * BSTR + n0]);
                bh[nt][1] = fbits(BbH[(kb + tig + 4) * BSTR + n0]);
                bl[nt][0] = fbits(BbL[(kb + tig    ) * BSTR + n0]);
                bl[nt][1] = fbits(BbL[(kb + tig + 4) * BSTR + n0]);
            }
#pragma unroll
            for (int mt = 0; mt < 4; mt++)
#pragma unroll
                for (int nt = 0; nt < 4; nt++) {
                    mma_tf32(acc[mt][nt], ah[mt], bh[nt][0], bh[nt][1]);
                    mma_tf32(acc[mt][nt], ah[mt], bl[nt][0], bl[nt][1]);
                    mma_tf32(acc[mt][nt], al[mt], bh[nt][0], bh[nt][1]);
                }
        }
        __syncthreads();
    }

    // Epilogue
#pragma unroll
    for (int mt = 0; mt < 4; mt++) {
        const int r0 = by * GBM + wm * 64 + mt * 16 + gID;
#pragma unroll
        for (int nt = 0; nt < 4; nt++) {
            const int c0 = bx * GBN + wn * 32 + nt * 8 + tig * 2;
            const float v00 = (acc[mt][nt][0] + bias[c0])     * scale;
            const float v01 = (acc[mt][nt][1] + bias[c0 + 1]) * scale;
            const float v10 = (acc[mt][nt][2] + bias[c0])     * scale;
            const float v11 = (acc[mt][nt][3] + bias[c0 + 1]) * scale;
            if (MODE == 0) {
                Chi[(size_t)r0 * E + c0]           = v00;
                Chi[(size_t)r0 * E + c0 + 1]       = v01;
                Chi[(size_t)(r0 + 8) * E + c0]     = v10;
                Chi[(size_t)(r0 + 8) * E + c0 + 1] = v11;
            } else {
                const int h = c0 / D, d = c0 % D;
                unsigned hu, lu;
                {
                    const int b = r0 / S, s = r0 % S;
                    const size_t p = ((((size_t)b * H + h) * S) + s) * D + d;
                    split_tf32(v00, hu, lu);
                    Chi[p] = __uint_as_float(hu); Clo[p] = __uint_as_float(lu);
                    split_tf32(v01, hu, lu);
                    Chi[p + 1] = __uint_as_float(hu); Clo[p + 1] = __uint_as_float(lu);
                }
                {
                    const int b = (r0 + 8) / S, s = (r0 + 8) % S;
                    const size_t p = ((((size_t)b * H + h) * S) + s) * D + d;
                    split_tf32(v10, hu, lu);
                    Chi[p] = __uint_as_float(hu); Clo[p] = __uint_as_float(lu);
                    split_tf32(v11, hu, lu);
                    Chi[p + 1] = __uint_as_float(hu); Clo[p + 1] = __uint_as_float(lu);
                }
            }
        }
    }
}

// ---------------------------------------------------------------------------
// Causal flash attention, Br=Bc=64, D=64. Q/K/V arrive pre-split (hi/lo).
// K/V double-buffered via cp.async. 256 threads, mma warp grid 2x4.
// Softmax scalar (16x16 threads). P split once at write. Output -> ctx hi/lo.
// smem (floats): QHI QLO | KHI[2] KLO[2] VHI[2] VLO[2] | PHI PLO | corr linv
// ---------------------------------------------------------------------------
constexpr int AST = 68;
constexpr int ABUF = 64 * AST;  // 4352 floats
constexpr int O_QHI = 0;
constexpr int O_QLO = ABUF;
constexpr int O_KHI = 2 * ABUF;   // [2]
constexpr int O_KLO = 4 * ABUF;   // [2]
constexpr int O_VHI = 6 * ABUF;   // [2]
constexpr int O_VLO = 8 * ABUF;   // [2]
constexpr int O_PHI = 10 * ABUF;
constexpr int O_PLO = 11 * ABUF;
constexpr int O_CORR = 12 * ABUF;       // [64]
constexpr int O_LINV = 12 * ABUF + 64;  // [64]
constexpr int ATT_SMEM_BYTES = (12 * ABUF + 128) * 4;  // 209408

__global__ __launch_bounds__(256) void flash_attn_kernel(
    const float* __restrict__ Qhi, const float* __restrict__ Qlo,
    const float* __restrict__ Khi, const float* __restrict__ Klo,
    const float* __restrict__ Vhi, const float* __restrict__ Vlo,
    float* __restrict__ Chi, float* __restrict__ Clo)
{
    extern __shared__ float sm[];

    const int tid = threadIdx.x;
    const int tx = tid % 16, ty = tid / 16;          // scalar phase
    const int warpId = tid >> 5, lane = tid & 31;    // mma phase
    const int wm = warpId >> 2, wn = warpId & 3;     // 2 x 4
    const int gID = lane >> 2, tig = lane & 3;

    const int qt = blockIdx.x;
    const int bh = blockIdx.y;
    const int b = bh / H, h = bh % H;

    const float* QhiB = Qhi + (size_t)bh * S * D;
    const float* QloB = Qlo + (size_t)bh * S * D;
    const float* KhiB = Khi + (size_t)bh * S * D;
    const float* KloB = Klo + (size_t)bh * S * D;
    const float* VhiB = Vhi + (size_t)bh * S * D;
    const float* VloB = Vlo + (size_t)bh * S * D;

    // tile loader helpers: 64 rows x 64 floats = 1024 float4 per stream
    auto load_pair = [&](int dst_off, const float* src, int row0) {
#pragma unroll
        for (int it = 0; it < 4; it++) {
            const int idx = tid + it * 256;
            const int r = idx >> 4;
            const int c = (idx & 15) * 4;
            unsigned d = (unsigned)__cvta_generic_to_shared(
                &sm[dst_off + r * AST + c]);
            CP_ASYNC16(d, src + (size_t)(row0 + r) * D + c);
        }
    };
    auto load_kv = [&](int kt, int buf) {
        load_pair(O_KHI + buf * ABUF, KhiB, kt * 64);
        load_pair(O_KLO + buf * ABUF, KloB, kt * 64);
        load_pair(O_VHI + buf * ABUF, VhiB, kt * 64);
        load_pair(O_VLO + buf * ABUF, VloB, kt * 64);
    };

    // Q (already scaled by 0.125 in projection) + first K/V
    load_pair(O_QHI, QhiB, qt * 64);
    load_pair(O_QLO, QloB, qt * 64);
    load_kv(0, 0);
    CP_COMMIT();

    float m_i[4], l_i[4];
#pragma unroll
    for (int i = 0; i < 4; i++) { m_i[i] = -1e30f; l_i[i] = 0.0f; }

    float oacc[2][2][4];
#pragma unroll
    for (int mt = 0; mt < 2; mt++)
#pragma unroll
        for (int nt = 0; nt < 2; nt++)
#pragma unroll
            for (int r = 0; r < 4; r++) oacc[mt][nt][r] = 0.0f;

    CP_WAIT0();
    __syncthreads();

    for (int kt = 0; kt <= qt; kt++) {
        const int buf = kt & 1;
        if (kt < qt) {
            load_kv(kt + 1, buf ^ 1);
            CP_COMMIT();
        }

        const float* KsH = sm + O_KHI + buf * ABUF;
        const float* KsL = sm + O_KLO + buf * ABUF;
        const float* VsH = sm + O_VHI + buf * ABUF;
        const float* VsL = sm + O_VLO + buf * ABUF;
        float* Ps  = sm + O_PHI;   // raw S, then p_hi
        float* PsL = sm + O_PLO;   // p_lo

        // ---- S = Qs @ K^T (3xTF32, pure LDS+HMMA) ----
        {
            float sacc[2][2][4];
#pragma unroll
            for (int mt = 0; mt < 2; mt++)
#pragma unroll
                for (int nt = 0; nt < 2; nt++)
#pragma unroll
                    for (int r = 0; r < 4; r++) sacc[mt][nt][r] = 0.0f;

#pragma unroll
            for (int k8 = 0; k8 < 8; k8++) {
                const int kb = k8 * 8;
                unsigned ah[2][4], al[2][4];
#pragma unroll
                for (int mt = 0; mt < 2; mt++) {
                    const int r0 = wm * 32 + mt * 16 + gID;
                    ah[mt][0] = fbits(sm[O_QHI + (r0    ) * AST + kb + tig    ]);
                    ah[mt][1] = fbits(sm[O_QHI + (r0 + 8) * AST + kb + tig    ]);
                    ah[mt][2] = fbits(sm[O_QHI + (r0    ) * AST + kb + tig + 4]);
                    ah[mt][3] = fbits(sm[O_QHI + (r0 + 8) * AST + kb + tig + 4]);
                    al[mt][0] = fbits(sm[O_QLO + (r0    ) * AST + kb + tig    ]);
                    al[mt][1] = fbits(sm[O_QLO + (r0 + 8) * AST + kb + tig    ]);
                    al[mt][2] = fbits(sm[O_QLO + (r0    ) * AST + kb + tig + 4]);
                    al[mt][3] = fbits(sm[O_QLO + (r0 + 8) * AST + kb + tig + 4]);
                }
                unsigned bhf[2][2], blf[2][2];
#pragma unroll
                for (int nt = 0; nt < 2; nt++) {
                    const int n0 = wn * 16 + nt * 8 + gID;
                    bhf[nt][0] = fbits(KsH[n0 * AST + kb + tig    ]);
                    bhf[nt][1] = fbits(KsH[n0 * AST + kb + tig + 4]);
                    blf[nt][0] = fbits(KsL[n0 * AST + kb + tig    ]);
                    blf[nt][1] = fbits(KsL[n0 * AST + kb + tig + 4]);
                }
#pragma unroll
                for (int mt = 0; mt < 2; mt++)
#pragma unroll
                    for (int nt = 0; nt < 2; nt++) {
                        mma_tf32(sacc[mt][nt], ah[mt], bhf[nt][0], bhf[nt][1]);
                        mma_tf32(sacc[mt][nt], ah[mt], blf[nt][0], blf[nt][1]);
                        mma_tf32(sacc[mt][nt], al[mt], bhf[nt][0], bhf[nt][1]);
                    }
            }
#pragma unroll
            for (int mt = 0; mt < 2; mt++) {
                const int r0 = wm * 32 + mt * 16 + gID;
#pragma unroll
                for (int nt = 0; nt < 2; nt++) {
                    const int c0 = wn * 16 + nt * 8 + tig * 2;
                    Ps[r0 * AST + c0]           = sacc[mt][nt][0];
                    Ps[r0 * AST + c0 + 1]       = sacc[mt][nt][1];
                    Ps[(r0 + 8) * AST + c0]     = sacc[mt][nt][2];
                    Ps[(r0 + 8) * AST + c0 + 1] = sacc[mt][nt][3];
                }
            }
        }
        __syncthreads();

        // ---- scalar online softmax; write p split (hi/lo) ----
        const bool diag = (kt == qt);
#pragma unroll
        for (int i = 0; i < 4; i++) {
            const int row = ty * 4 + i;
            float sv[4];
#pragma unroll
            for (int j = 0; j < 4; j++) {
                float s = Ps[row * AST + tx * 4 + j];
                if (diag && (tx * 4 + j) > row) s = -1e30f;
                sv[j] = s;
            }
            float rmax = fmaxf(fmaxf(sv[0], sv[1]), fmaxf(sv[2], sv[3]));
#pragma unroll
            for (int off = 8; off >= 1; off >>= 1)
                rmax = fmaxf(rmax, __shfl_xor_sync(0xffffffffu, rmax, off));
            const float m_new = fmaxf(m_i[i], rmax);
            const float corr = __expf(m_i[i] - m_new);
            float rsum = 0.0f;
#pragma unroll
            for (int j = 0; j < 4; j++) {
                const float p = __expf(sv[j] - m_new);
                rsum += p;
                unsigned hu, lu;
                split_tf32(p, hu, lu);
                Ps [row * AST + tx * 4 + j] = __uint_as_float(hu);
                PsL[row * AST + tx * 4 + j] = __uint_as_float(lu);
            }
#pragma unroll
            for (int off = 8; off >= 1; off >>= 1)
                rsum += __shfl_xor_sync(0xffffffffu, rsum, off);
            l_i[i] = l_i[i] * corr + rsum;
            m_i[i] = m_new;
            if (tx == 0) sm[O_CORR + row] = corr;
        }
        __syncthreads();

        // ---- O = O*corr + P @ V (3xTF32, pure LDS+HMMA) ----
#pragma unroll
        for (int mt = 0; mt < 2; mt++) {
            const int r0 = wm * 32 + mt * 16 + gID;
            const float cl = sm[O_CORR + r0];
            const float ch = sm[O_CORR + r0 + 8];
#pragma unroll
            for (int nt = 0; nt < 2; nt++) {
                oacc[mt][nt][0] *= cl; oacc[mt][nt][1] *= cl;
                oacc[mt][nt][2] *= ch; oacc[mt][nt][3] *= ch;
            }
        }
#pragma unroll
        for (int k8 = 0; k8 < 8; k8++) {
            const int kb = k8 * 8;
            unsigned ah[2][4], al[2][4];
#pragma unroll
            for (int mt = 0; mt < 2; mt++) {
                const int r0 = wm * 32 + mt * 16 + gID;
                ah[mt][0] = fbits(Ps [(r0    ) * AST + kb + tig    ]);
                ah[mt][1] = fbits(Ps [(r0 + 8) * AST + kb + tig    ]);
                ah[mt][2] = fbits(Ps [(r0    ) * AST + kb + tig + 4]);
                ah[mt][3] = fbits(Ps [(r0 + 8) * AST + kb + tig + 4]);
                al[mt][0] = fbits(PsL[(r0    ) * AST + kb + tig    ]);
                al[mt][1] = fbits(PsL[(r0 + 8) * AST + kb + tig    ]);
                al[mt][2] = fbits(PsL[(r0    ) * AST + kb + tig + 4]);
                al[mt][3] = fbits(PsL[(r0 + 8) * AST + kb + tig + 4]);
            }
            unsigned bhf[2][2], blf[2][2];
#pragma unroll
            for (int nt = 0; nt < 2; nt++) {
                const int n0 = wn * 16 + nt * 8 + gID;
                bhf[nt][0] = fbits(VsH[(kb + tig    ) * AST + n0]);
                bhf[nt][1] = fbits(VsH[(kb + tig + 4) * AST + n0]);
                blf[nt][0] = fbits(VsL[(kb + tig    ) * AST + n0]);
                blf[nt][1] = fbits(VsL[(kb + tig + 4) * AST + n0]);
            }
#pragma unroll
            for (int mt = 0; mt < 2; mt++)
#pragma unroll
                for (int nt = 0; nt < 2; nt++) {
                    mma_tf32(oacc[mt][nt], ah[mt], bhf[nt][0], bhf[nt][1]);
                    mma_tf32(oacc[mt][nt], ah[mt], blf[nt][0], blf[nt][1]);
                    mma_tf32(oacc[mt][nt], al[mt], bhf[nt][0], bhf[nt][1]);
                }
        }

        if (kt < qt) CP_WAIT0();
        __syncthreads();   // all warps done with P/V before next S-write / KV overwrite
    }

    // publish 1/l
#pragma unroll
    for (int i = 0; i < 4; i++)
        if (tx == 0) sm[O_LINV + ty * 4 + i] = 1.0f / l_i[i];
    __syncthreads();

    // write ctx pre-split: (B,S,E)
#pragma unroll
    for (int mt = 0; mt < 2; mt++) {
        const int r0 = wm * 32 + mt * 16 + gID;
        const float il = sm[O_LINV + r0];
        const float ih = sm[O_LINV + r0 + 8];
#pragma unroll
        for (int nt = 0; nt < 2; nt++) {
            const int c0 = wn * 16 + nt * 8 + tig * 2;
            const size_t p0 = ((size_t)b * S + qt * 64 + r0) * E + h * D + c0;
            const size_t p1 = ((size_t)b * S + qt * 64 + r0 + 8) * E + h * D + c0;
            unsigned hu, lu;
            split_tf32(oacc[mt][nt][0] * il, hu, lu);
            Chi[p0]     = __uint_as_float(hu); Clo[p0]     = __uint_as_float(lu);
            split_tf32(oacc[mt][nt][1] * il, hu, lu);
            Chi[p0 + 1] = __uint_as_float(hu); Clo[p0 + 1] = __uint_as_float(lu);
            split_tf32(oacc[mt][nt][2] * ih, hu, lu);
            Chi[p1]     = __uint_as_float(hu); Clo[p1]     = __uint_as_float(lu);
            split_tf32(oacc[mt][nt][3] * ih, hu, lu);
            Chi[p1 + 1] = __uint_as_float(hu); Clo[p1 + 1] = __uint_as_float(lu);
        }
    }
}

// ---------------------------------------------------------------------------
extern "C" void kernel_launch(void* const* d_in, const int* in_sizes, int n_in,
                              void* d_out, int out_size)
{
    const float* x  = (const float*)d_in[0];
    const float* Wq = (const float*)d_in[1];
    const float* bq = (const float*)d_in[2];
    const float* Wk = (const float*)d_in[3];
    const float* bk = (const float*)d_in[4];
    const float* Wv = (const float*)d_in[5];
    const float* bv = (const float*)d_in[6];
    const float* Wo = (const float*)d_in[7];
    const float* bo = (const float*)d_in[8];
    float* out = (float*)d_out;

    float *xhi, *xlo, *Whi, *Wlo, *qhi, *qlo, *khi, *klo, *vhi, *vlo, *chi, *clo;
    cudaGetSymbolAddress((void**)&xhi, g_xhi);
    cudaGetSymbolAddress((void**)&xlo, g_xlo);
    cudaGetSymbolAddress((void**)&Whi, g_Whi);
    cudaGetSymbolAddress((void**)&Wlo, g_Wlo);
    cudaGetSymbolAddress((void**)&qhi, g_qhi);
    cudaGetSymbolAddress((void**)&qlo, g_qlo);
    cudaGetSymbolAddress((void**)&khi, g_khi);
    cudaGetSymbolAddress((void**)&klo, g_klo);
    cudaGetSymbolAddress((void**)&vhi, g_vhi);
    cudaGetSymbolAddress((void**)&vlo, g_vlo);
    cudaGetSymbolAddress((void**)&chi, g_chi);
    cudaGetSymbolAddress((void**)&clo, g_clo);

    cudaFuncSetAttribute(gemm3_kernel<0>,
                         cudaFuncAttributeMaxDynamicSharedMemorySize, GEMM_SMEM_BYTES);
    cudaFuncSetAttribute(gemm3_kernel<1>,
                         cudaFuncAttributeMaxDynamicSharedMemorySize, GEMM_SMEM_BYTES);
    cudaFuncSetAttribute(flash_attn_kernel,
                         cudaFuncAttributeMaxDynamicSharedMemorySize, ATT_SMEM_BYTES);

    const size_t EE = (size_t)E * E;

    // Pre-split x and the four weight matrices
    split_kernel<<<(M_ROWS * E / 4 + 255) / 256, 256>>>(x, xhi, xlo, M_ROWS * E / 4);
    split_kernel<<<(int)(EE / 4 + 255) / 256, 256>>>(Wq, Whi + 0 * EE, Wlo + 0 * EE, (int)(EE / 4));
    split_kernel<<<(int)(EE / 4 + 255) / 256, 256>>>(Wk, Whi + 1 * EE, Wlo + 1 * EE, (int)(EE / 4));
    split_kernel<<<(int)(EE / 4 + 255) / 256, 256>>>(Wv, Whi + 2 * EE, Wlo + 2 * EE, (int)(EE / 4));
    split_kernel<<<(int)(EE / 4 + 255) / 256, 256>>>(Wo, Whi + 3 * EE, Wlo + 3 * EE, (int)(EE / 4));

    dim3 gemm_grid(E / GBN, M_ROWS / GBM);   // (8, 64)
    // Q projection: fold 1/sqrt(D) = 0.125 into q
    gemm3_kernel<1><<<gemm_grid, 256, GEMM_SMEM_BYTES>>>(
        xhi, xlo, Whi + 0 * EE, Wlo + 0 * EE, bq, 0.125f, qhi, qlo);
    gemm3_kernel<1><<<gemm_grid, 256, GEMM_SMEM_BYTES>>>(
        xhi, xlo, Whi + 1 * EE, Wlo + 1 * EE, bk, 1.0f, khi, klo);
    gemm3_kernel<1><<<gemm_grid, 256, GEMM_SMEM_BYTES>>>(
        xhi, xlo, Whi + 2 * EE, Wlo + 2 * EE, bv, 1.0f, vhi, vlo);

    dim3 attn_grid(S / 64, B * H);           // (32, 64)
    flash_attn_kernel<<<attn_grid, 256, ATT_SMEM_BYTES>>>(
        qhi, qlo, khi, klo, vhi, vlo, chi, clo);

    gemm3_kernel<0><<<gemm_grid, 256, GEMM_SMEM_BYTES>>>(
        chi, clo, Whi + 3 * EE, Wlo + 3 * EE, bo, 1.0f, out, nullptr);
}